// round 5
// baseline (speedup 1.0000x reference)
#include <cuda_runtime.h>
#include <cuda_bf16.h>
#include <cstdint>
#include <cstddef>

#define BB  128
#define SS  512
#define EE  128
#define HH  256
#define HD  512
#define TT  127

// ------------------------- device scratch ------------------------------------
__device__ float g_embSB[(size_t)SS*BB*EE];
__device__ float g_embTB[(size_t)TT*BB*EE];
__device__ float g_xw_f[(size_t)SS*BB*4*HH];
__device__ float g_xw_b[(size_t)SS*BB*4*HH];
__device__ float g_h_enc[2][2][BB*HH];           // [parity][dir]
__device__ float g_c_enc[2][BB*HH];              // final cells [dir]
__device__ float g_encout[(size_t)BB*SS*2*HH];   // (b,s,512)
__device__ float g_encproj[(size_t)BB*SS*HD];    // (b,s,512) + attn_b
__device__ float g_xg[(size_t)TT*BB*4*HD];       // dec emb gates + dec_b
__device__ float g_wcat[(size_t)4*HD*1024];      // [Wih_ctx | Whh] (2048x1024)
__device__ float g_u[BB*1024];                   // [ctx(512) | h(512)]
__device__ float g_gates[BB*4*HD];
__device__ float g_q[BB*HD];

// barrier state (zero-init; counters return to 0, gens monotonic)
__device__ unsigned g_ebar_cnt[512];
__device__ volatile unsigned g_ebar_gen[512];
__device__ unsigned g_dbar_cnt;
__device__ volatile unsigned g_dbar_gen;

// ------------------------- helpers -------------------------------------------
__device__ __forceinline__ float ftanh(float x){
    float e = __expf(2.f*x);
    return 1.f - __fdividef(2.f, e + 1.f);
}
__device__ __forceinline__ float fsig(float x){
    return __fdividef(1.f, 1.f + __expf(-x));
}

__device__ __forceinline__ void sys_barrier(unsigned* cnt, volatile unsigned* gen,
                                            unsigned n){
    __syncthreads();
    if (threadIdx.x == 0){
        unsigned g = *gen;
        __threadfence();
        if (atomicAdd(cnt, 1u) == n - 1u){
            *cnt = 0u;
            __threadfence();
            *gen = g + 1u;
        } else {
            while (*gen == g) __nanosleep(64);
            __threadfence();
        }
    }
    __syncthreads();
}

// ------------------------- generic SGEMM (precompute only) -------------------
template<int BM,int BN,int BK,int TM,int TN,bool BT>
__global__ void __launch_bounds__((BM/TM)*(BN/TN))
sgemm(const float* __restrict__ A, const float* __restrict__ Bw,
      const float* __restrict__ bias, float* __restrict__ C,
      int K, int lda, int ldb, int ldc)
{
    constexpr int TX = BN/TN, TY = BM/TM, NT = TX*TY;
    __shared__ float As[BK][BM+1];
    __shared__ float Bs[BK][BN+1];
    const int n0 = blockIdx.x * BN;
    const int m0 = blockIdx.y * BM;
    const int tid = threadIdx.x;
    const int tx = tid % TX, ty = tid / TX;
    float acc[TM][TN];
#pragma unroll
    for (int i=0;i<TM;i++)
#pragma unroll
        for (int j=0;j<TN;j++) acc[i][j]=0.f;

    for (int k0=0; k0<K; k0+=BK){
#pragma unroll 4
        for (int i = tid; i < BM*BK; i += NT){
            int mm = i / BK, kk = i % BK;
            As[kk][mm] = A[(size_t)(m0+mm)*lda + k0 + kk];
        }
        if (BT){
#pragma unroll 4
            for (int i = tid; i < BN*BK; i += NT){
                int nn = i / BK, kk = i % BK;
                Bs[kk][nn] = Bw[(size_t)(n0+nn)*ldb + k0 + kk];
            }
        } else {
#pragma unroll 4
            for (int i = tid; i < BN*BK; i += NT){
                int kk = i / BN, nn = i % BN;
                Bs[kk][nn] = Bw[(size_t)(k0+kk)*ldb + n0 + nn];
            }
        }
        __syncthreads();
#pragma unroll
        for (int kk=0; kk<BK; kk++){
            float a[TM], bv[TN];
#pragma unroll
            for (int i=0;i<TM;i++) a[i] = As[kk][ty + TY*i];
#pragma unroll
            for (int j=0;j<TN;j++) bv[j] = Bs[kk][tx + TX*j];
#pragma unroll
            for (int i=0;i<TM;i++)
#pragma unroll
                for (int j=0;j<TN;j++) acc[i][j] = fmaf(a[i], bv[j], acc[i][j]);
        }
        __syncthreads();
    }
#pragma unroll
    for (int i=0;i<TM;i++){
        int m = m0 + ty + TY*i;
#pragma unroll
        for (int j=0;j<TN;j++){
            int n = n0 + tx + TX*j;
            float v = acc[i][j];
            if (bias) v += bias[n];
            C[(size_t)m*ldc + n] = v;
        }
    }
}

// ------------------------- prep kernels --------------------------------------
__global__ void k_init(float* __restrict__ out){
    int idx = blockIdx.x*blockDim.x + threadIdx.x;      // 65536
    (&g_h_enc[0][0][0])[idx] = 0.f;                     // parity 0, both dirs
    if (idx < BB*128){
        int b = idx >> 7, v = idx & 127;
        out[(size_t)b*128*128 + v] = 0.f;               // out[:,0,:] = 0
    }
}

__global__ void k_gather_src(const int* __restrict__ src,
                             const float* __restrict__ enc_emb){
    size_t idx = (size_t)blockIdx.x*blockDim.x + threadIdx.x;
    if (idx >= (size_t)SS*BB*EE) return;
    int e = idx & 127;
    int b = (idx >> 7) & 127;
    int s = idx >> 14;
    g_embSB[idx] = enc_emb[(size_t)src[b*SS + s]*EE + e];
}

__global__ void k_gather_trg(const int* __restrict__ trg,
                             const float* __restrict__ dec_emb){
    size_t idx = (size_t)blockIdx.x*blockDim.x + threadIdx.x;
    if (idx >= (size_t)TT*BB*EE) return;
    int e = idx & 127;
    int b = (idx >> 7) & 127;
    int t = idx >> 14;
    g_embTB[idx] = dec_emb[(size_t)trg[b*128 + t]*EE + e];
}

__global__ void k_pack_wcat(const float* __restrict__ dec_Wih,
                            const float* __restrict__ dec_Whh){
    int idx = blockIdx.x*blockDim.x + threadIdx.x;   // 2048*1024
    int n = idx >> 10, k = idx & 1023;
    float v = (k < 512) ? dec_Wih[(size_t)n*640 + 128 + k]
                        : dec_Whh[(size_t)n*512 + (k - 512)];
    g_wcat[idx] = v;
}

// ------------------------- persistent encoder --------------------------------
// 128 blocks x 128 threads. block = dir(1) | bt(3) | jt(3).
// j-tile = 32 cells (x4 gates), b-tile = 16 rows. Whh slice cached in smem once.
// c lives in registers for the whole sequence. 8-block group barrier per step.
__global__ void __launch_bounds__(128)
k_encoder(const float* __restrict__ Whh_f, const float* __restrict__ Whh_b)
{
    extern __shared__ float ws[];        // 256*129 floats
    __shared__ float hs[16][17];
    const int bx  = blockIdx.x;
    const int jt  = bx & 7, bt = (bx >> 3) & 7, dir = bx >> 6;
    const int grp = dir*8 + bt;
    const int j0  = jt*32, b0 = bt*16;
    const int tid = threadIdx.x;
    const int tx  = tid & 31, ty = tid >> 5;
    const float* __restrict__ Whh = dir ? Whh_b : Whh_f;
    const float* __restrict__ xw  = dir ? g_xw_b : g_xw_f;

    // cache weight slice: ws[k*129 + g*32 + jj] (coalesced over k)
    for (int i = tid; i < 32768; i += 128){
        int k = i & 255, nl = i >> 8;
        ws[k*129 + nl] = Whh[(size_t)((nl>>5)*256 + j0 + (nl&31))*256 + k];
    }
    __syncthreads();

    float cr[4] = {0.f, 0.f, 0.f, 0.f};
    int p = 0;
    const int j = j0 + tx;

    for (int s = 0; s < 512; s++){
        const int sa = dir ? (511 - s) : s;
        const float* __restrict__ hin = g_h_enc[p][dir];
        float acc[4][4];
#pragma unroll
        for (int g=0; g<4; g++)
#pragma unroll
            for (int bi=0; bi<4; bi++) acc[g][bi] = 0.f;

        for (int k0 = 0; k0 < 256; k0 += 16){
            {
                int kk0 = tid & 15, bb0 = tid >> 4;
                hs[kk0][bb0] = hin[(b0+bb0)*256 + k0 + kk0];
                int i1 = tid + 128;
                int kk1 = i1 & 15, bb1 = i1 >> 4;
                hs[kk1][bb1] = hin[(b0+bb1)*256 + k0 + kk1];
            }
            __syncthreads();
#pragma unroll
            for (int kk = 0; kk < 16; kk++){
                const float* w = ws + (size_t)(k0+kk)*129;
                float a0 = hs[kk][ty],   a1 = hs[kk][ty+4];
                float a2 = hs[kk][ty+8], a3 = hs[kk][ty+12];
                float w0 = w[tx], w1 = w[32+tx], w2 = w[64+tx], w3 = w[96+tx];
                acc[0][0]=fmaf(w0,a0,acc[0][0]); acc[0][1]=fmaf(w0,a1,acc[0][1]);
                acc[0][2]=fmaf(w0,a2,acc[0][2]); acc[0][3]=fmaf(w0,a3,acc[0][3]);
                acc[1][0]=fmaf(w1,a0,acc[1][0]); acc[1][1]=fmaf(w1,a1,acc[1][1]);
                acc[1][2]=fmaf(w1,a2,acc[1][2]); acc[1][3]=fmaf(w1,a3,acc[1][3]);
                acc[2][0]=fmaf(w2,a0,acc[2][0]); acc[2][1]=fmaf(w2,a1,acc[2][1]);
                acc[2][2]=fmaf(w2,a2,acc[2][2]); acc[2][3]=fmaf(w2,a3,acc[2][3]);
                acc[3][0]=fmaf(w3,a0,acc[3][0]); acc[3][1]=fmaf(w3,a1,acc[3][1]);
                acc[3][2]=fmaf(w3,a2,acc[3][2]); acc[3][3]=fmaf(w3,a3,acc[3][3]);
            }
            __syncthreads();
        }

        float* __restrict__ hout = g_h_enc[p^1][dir];
#pragma unroll
        for (int bi = 0; bi < 4; bi++){
            int b = b0 + ty + 4*bi;
            const float* xwb = xw + ((size_t)sa*128 + b)*1024 + j;
            float ig = fsig (acc[0][bi] + xwb[0]);
            float fg = fsig (acc[1][bi] + xwb[256]);
            float gg = ftanh(acc[2][bi] + xwb[512]);
            float og = fsig (acc[3][bi] + xwb[768]);
            float cn = fmaf(fg, cr[bi], ig*gg);
            cr[bi] = cn;
            float hn = og * ftanh(cn);
            hout[b*256 + j] = hn;
            g_encout[((size_t)b*512 + sa)*512 + dir*256 + j] = hn;
        }
        p ^= 1;
        if (s < 511){
            sys_barrier(&g_ebar_cnt[grp*32], &g_ebar_gen[grp*32], 8u);
        } else {
#pragma unroll
            for (int bi = 0; bi < 4; bi++)
                g_c_enc[dir][(b0 + ty + 4*bi)*256 + j] = cr[bi];
        }
    }
}

// ------------------------- decoder tile GEMM ---------------------------------
// BM=32 fixed, 256 threads (16x16), TM=2. BN/TN template.
template<int BN,int TN>
__device__ void tile_gemm(const float* __restrict__ A, int lda,
                          const float* __restrict__ B, int ldb, bool bt, int K,
                          int m0, int n0,
                          const float* __restrict__ bias,
                          const float* __restrict__ Dadd, int ldd,
                          float* __restrict__ C, int ldc)
{
    __shared__ float As[16][33];
    __shared__ float Bs[16][BN+1];
    const int tid = threadIdx.x;
    const int tx = tid & 15, ty = tid >> 4;
    float acc[2][TN];
#pragma unroll
    for (int i=0;i<2;i++)
#pragma unroll
        for (int j=0;j<TN;j++) acc[i][j]=0.f;

    for (int k0 = 0; k0 < K; k0 += 16){
#pragma unroll
        for (int i = tid; i < 512; i += 256){
            int mm = i >> 4, kk = i & 15;
            As[kk][mm] = A[(size_t)(m0+mm)*lda + k0 + kk];
        }
        if (bt){
#pragma unroll
            for (int i = tid; i < 16*BN; i += 256){
                int nn = i >> 4, kk = i & 15;
                Bs[kk][nn] = B[(size_t)(n0+nn)*ldb + k0 + kk];
            }
        } else {
#pragma unroll
            for (int i = tid; i < 16*BN; i += 256){
                int kk = i / BN, nn = i % BN;
                Bs[kk][nn] = B[(size_t)(k0+kk)*ldb + n0 + nn];
            }
        }
        __syncthreads();
#pragma unroll
        for (int kk = 0; kk < 16; kk++){
            float a0 = As[kk][ty], a1 = As[kk][ty+16];
#pragma unroll
            for (int j = 0; j < TN; j++){
                float bv = Bs[kk][tx + 16*j];
                acc[0][j] = fmaf(a0, bv, acc[0][j]);
                acc[1][j] = fmaf(a1, bv, acc[1][j]);
            }
        }
        __syncthreads();
    }
#pragma unroll
    for (int i = 0; i < 2; i++){
        int m = m0 + ty + 16*i;
#pragma unroll
        for (int j = 0; j < TN; j++){
            int n = n0 + tx + 16*j;
            float v = acc[i][j];
            if (bias) v += bias[n];
            if (Dadd) v += Dadd[(size_t)m*ldd + n];
            C[(size_t)m*ldc + n] = v;
        }
    }
}

// ------------------------- decoder attention ---------------------------------
__device__ void attention(int b, const float* __restrict__ attn_v)
{
    __shared__ float qsh[512];
    __shared__ float sc[512];
    __shared__ float red[8];
    const int tid = threadIdx.x, lane = tid & 31, warp = tid >> 5;

    for (int e = tid; e < 512; e += 256) qsh[e] = g_q[b*512 + e];
    __syncthreads();

    float av[16];
#pragma unroll
    for (int i = 0; i < 16; i++) av[i] = attn_v[lane + 32*i];

    const float* __restrict__ proj = g_encproj + (size_t)b*512*512;
    for (int s = warp; s < 512; s += 8){
        const float* pr = proj + (size_t)s*512;
        float acc = 0.f;
#pragma unroll
        for (int i = 0; i < 16; i++){
            int e = lane + 32*i;
            acc = fmaf(av[i], ftanh(qsh[e] + pr[e]), acc);
        }
#pragma unroll
        for (int o = 16; o; o >>= 1) acc += __shfl_xor_sync(~0u, acc, o);
        if (lane == 0) sc[s] = acc;
    }
    __syncthreads();

    float v0 = sc[tid], v1 = sc[tid + 256];
    float m = fmaxf(v0, v1);
#pragma unroll
    for (int o = 16; o; o >>= 1) m = fmaxf(m, __shfl_xor_sync(~0u, m, o));
    if (lane == 0) red[warp] = m;
    __syncthreads();
    m = red[0];
#pragma unroll
    for (int i = 1; i < 8; i++) m = fmaxf(m, red[i]);
    __syncthreads();
    float e0 = __expf(v0 - m), e1 = __expf(v1 - m);
    float ssum = e0 + e1;
#pragma unroll
    for (int o = 16; o; o >>= 1) ssum += __shfl_xor_sync(~0u, ssum, o);
    if (lane == 0) red[warp] = ssum;
    __syncthreads();
    ssum = 0.f;
#pragma unroll
    for (int i = 0; i < 8; i++) ssum += red[i];
    float inv = __fdividef(1.f, ssum);
    sc[tid] = e0*inv;
    sc[tid + 256] = e1*inv;
    __syncthreads();

    const float* __restrict__ eo = g_encout + (size_t)b*512*512;
    float c0 = 0.f, c1 = 0.f;
#pragma unroll 8
    for (int s = 0; s < 512; s++){
        float w = sc[s];
        c0 = fmaf(w, eo[(size_t)s*512 + tid],       c0);
        c1 = fmaf(w, eo[(size_t)s*512 + tid + 256], c1);
    }
    g_u[b*1024 + tid]       = c0;
    g_u[b*1024 + tid + 256] = c1;
    __syncthreads();
}

__device__ __forceinline__ void dbar(){
    sys_barrier(&g_dbar_cnt, &g_dbar_gen, 128u);
}

// ------------------------- persistent decoder --------------------------------
// 128 blocks x 256 threads. Per step:
//  A: q = h@Wh (64 tiles) + logits(prev h) -> out[:,t] (16 tiles, t>0)
//  B: attention (block = batch row) -> ctx in g_u[:,0:512]
//  C: gates = [ctx|h]@wcat^T + xg[t] (128 tiles 32x64)
//  D: LSTM cell (c in registers), h -> g_u[:,512:1024]
__global__ void __launch_bounds__(256)
k_decoder(const float* __restrict__ attn_W, const float* __restrict__ attn_v,
          const float* __restrict__ out_W, const float* __restrict__ out_b,
          float* __restrict__ out)
{
    const int bid = blockIdx.x, tid = threadIdx.x;
    float cr[2];
#pragma unroll
    for (int r = 0; r < 2; r++){
        int idx = bid*256 + tid + r*32768;
        int b = idx >> 9, j = idx & 511;
        float h, c;
        if (j < 256){ h = g_h_enc[0][0][b*256 + j];       c = g_c_enc[0][b*256 + j]; }
        else        { h = g_h_enc[0][1][b*256 + j - 256]; c = g_c_enc[1][b*256 + j - 256]; }
        g_u[b*1024 + 512 + j] = h;
        cr[r] = c;
    }
    dbar();

    for (int t = 0; t < TT; t++){
        // ---- phase A ----
        if (bid < 64){
            int mt = bid & 3, nt = bid >> 2;
            tile_gemm<32,2>(g_u + 512, 1024, attn_W, 512, false, 512,
                            mt*32, nt*32, nullptr, nullptr, 0, g_q, 512);
        } else if (bid < 80 && t > 0){
            int q = bid - 64, mt = q & 3, nt = q >> 2;
            tile_gemm<32,2>(g_u + 512, 1024, out_W, 128, false, 512,
                            mt*32, nt*32, out_b, nullptr, 0,
                            out + (size_t)t*128, 128*128);
        }
        dbar();
        // ---- phase B ----
        attention(bid, attn_v);
        dbar();
        // ---- phase C ----
        {
            int mt = bid & 3, nt = bid >> 2;
            tile_gemm<64,4>(g_u, 1024, g_wcat, 1024, true, 1024,
                            mt*32, nt*64, nullptr,
                            g_xg + (size_t)t*BB*2048, 2048, g_gates, 2048);
        }
        dbar();
        // ---- phase D ----
#pragma unroll
        for (int r = 0; r < 2; r++){
            int idx = bid*256 + tid + r*32768;
            int b = idx >> 9, j = idx & 511;
            const float* gg = g_gates + b*2048;
            float ig = fsig (gg[j]);
            float fg = fsig (gg[512  + j]);
            float g2 = ftanh(gg[1024 + j]);
            float og = fsig (gg[1536 + j]);
            float cn = fmaf(fg, cr[r], ig*g2);
            cr[r] = cn;
            g_u[b*1024 + 512 + j] = og * ftanh(cn);
        }
        dbar();
    }
    // final logits -> out[:, 127]
    if (bid < 16){
        int mt = bid & 3, nt = bid >> 2;
        tile_gemm<32,2>(g_u + 512, 1024, out_W, 128, false, 512,
                        mt*32, nt*32, out_b, nullptr, 0,
                        out + (size_t)TT*128, 128*128);
    }
}

// ------------------------- launch --------------------------------------------
extern "C" void kernel_launch(void* const* d_in, const int* in_sizes, int n_in,
                              void* d_out, int out_size)
{
    const int*   src     = (const int*)  d_in[0];
    const int*   trg     = (const int*)  d_in[1];
    const float* enc_emb = (const float*)d_in[2];
    const float* Wih_f   = (const float*)d_in[3];
    const float* Whh_f   = (const float*)d_in[4];
    const float* b_f     = (const float*)d_in[5];
    const float* Wih_b   = (const float*)d_in[6];
    const float* Whh_b   = (const float*)d_in[7];
    const float* b_b     = (const float*)d_in[8];
    const float* dec_emb = (const float*)d_in[9];
    const float* dec_Wih = (const float*)d_in[10];
    const float* dec_Whh = (const float*)d_in[11];
    const float* dec_b   = (const float*)d_in[12];
    const float* attn_W  = (const float*)d_in[13];
    const float* attn_b  = (const float*)d_in[14];
    const float* attn_v  = (const float*)d_in[15];
    const float* out_W   = (const float*)d_in[16];
    const float* out_b   = (const float*)d_in[17];
    float* out = (float*)d_out;

    float *p_embSB, *p_embTB, *p_xw_f, *p_xw_b, *p_encout, *p_encproj, *p_xg;
    cudaGetSymbolAddress((void**)&p_embSB,  g_embSB);
    cudaGetSymbolAddress((void**)&p_embTB,  g_embTB);
    cudaGetSymbolAddress((void**)&p_xw_f,   g_xw_f);
    cudaGetSymbolAddress((void**)&p_xw_b,   g_xw_b);
    cudaGetSymbolAddress((void**)&p_encout, g_encout);
    cudaGetSymbolAddress((void**)&p_encproj,g_encproj);
    cudaGetSymbolAddress((void**)&p_xg,     g_xg);

    static bool attr_set = false;
    if (!attr_set){
        cudaFuncSetAttribute(k_encoder,
            cudaFuncAttributeMaxDynamicSharedMemorySize, 256*129*4);
        attr_set = true;
    }

    // ---- prep (4 nodes) ----
    k_init<<<256, 256>>>(out);
    k_gather_src<<<(SS*BB*EE + 255)/256, 256>>>(src, enc_emb);
    k_gather_trg<<<(TT*BB*EE + 255)/256, 256>>>(trg, dec_emb);
    k_pack_wcat<<<(2048*1024)/256, 256>>>(dec_Wih, dec_Whh);

    // ---- precompute GEMMs (3 nodes) ----
    sgemm<64,64,16,4,4,true><<<dim3(1024/64, (SS*BB)/64), 256>>>(
        p_embSB, Wih_f, b_f, p_xw_f, EE, EE, EE, 1024);
    sgemm<64,64,16,4,4,true><<<dim3(1024/64, (SS*BB)/64), 256>>>(
        p_embSB, Wih_b, b_b, p_xw_b, EE, EE, EE, 1024);
    sgemm<64,64,16,4,4,true><<<dim3(2048/64, (TT*BB)/64), 256>>>(
        p_embTB, dec_Wih, dec_b, p_xg, EE, EE, 640, 2048);

    // ---- persistent encoder (1 node) ----
    k_encoder<<<128, 128, 256*129*4>>>(Whh_f, Whh_b);

    // ---- enc_proj = enc_out @ We + attn_b (1 node) ----
    sgemm<64,64,16,4,4,false><<<dim3(512/64, (BB*SS)/64), 256>>>(
        p_encout, attn_W + 512*512, attn_b, p_encproj, 512, 512, 512, 512);

    // ---- persistent decoder (1 node) ----
    k_decoder<<<128, 256>>>(attn_W, attn_v, out_W, out_b, out);
}

// round 7
// speedup vs baseline: 1.0471x; 1.0471x over previous
#include <cuda_runtime.h>
#include <cuda_bf16.h>
#include <cstdint>
#include <cstddef>

#define BB  128
#define SS  512
#define EE  128
#define HH  256
#define HD  512
#define TT  127

typedef unsigned long long ull;

// ------------------------- device scratch ------------------------------------
__device__ float g_embSB[(size_t)SS*BB*EE];
__device__ float g_embTB[(size_t)TT*BB*EE];
__device__ float g_xw_f[(size_t)SS*BB*4*HH];
__device__ float g_xw_b[(size_t)SS*BB*4*HH];
__device__ float g_h_enc[2][2][BB*HH];                 // [parity][dir]
__device__ float g_c_enc[2][BB*HH];                    // final cells [dir]
__device__ float g_encout[(size_t)BB*SS*2*HH];         // fp32 (b,s,512)
__device__ __nv_bfloat162 g_encout_bf[(size_t)BB*SS*256]; // bf16 copy for ctx
__device__ __nv_bfloat162 g_encproj[(size_t)BB*SS*256];   // bf16 (b,s,512)+attn_b
__device__ float g_xg[(size_t)TT*BB*4*HD];             // dec emb gates + dec_b
__device__ float g_wcat[(size_t)4*HD*1024];            // [Wih_ctx | Whh]
__device__ float g_u[BB*1024];                         // [ctx(512) | h(512)]
__device__ float g_gates[BB*4*HD];
__device__ float g_q[BB*HD];

// decoder barrier (zero-init; counter returns to 0, gen monotonic)
__device__ unsigned g_dbar_cnt;
__device__ volatile unsigned g_dbar_gen;

// ------------------------- math helpers --------------------------------------
__device__ __forceinline__ float ftanh(float x){          // exact-ish (LSTM)
    float e = __expf(2.f*x);
    return 1.f - __fdividef(2.f, e + 1.f);
}
__device__ __forceinline__ float fsig(float x){
    return __fdividef(1.f, 1.f + __expf(-x));
}
__device__ __forceinline__ float tanha(float x){           // HW tanh (attention)
    float y; asm("tanh.approx.f32 %0, %1;" : "=f"(y) : "f"(x)); return y;
}
__device__ __forceinline__ ull fdup(float x){
    ull r; asm("mov.b64 %0, {%1, %1};" : "=l"(r) : "f"(x)); return r;
}
__device__ __forceinline__ void fma2(ull& d, ull a, ull b){
    asm("fma.rn.f32x2 %0, %1, %2, %0;" : "+l"(d) : "l"(a), "l"(b));
}
__device__ __forceinline__ float2 upk(ull v){
    float2 f; asm("mov.b64 {%0, %1}, %2;" : "=f"(f.x), "=f"(f.y) : "l"(v));
    return f;
}

__device__ __forceinline__ void dbar(){
    __syncthreads();
    if (threadIdx.x == 0){
        unsigned g = g_dbar_gen;
        __threadfence();
        if (atomicAdd(&g_dbar_cnt, 1u) == 127u){
            g_dbar_cnt = 0u;
            __threadfence();
            g_dbar_gen = g + 1u;
        } else {
            while (g_dbar_gen == g) __nanosleep(32);
            __threadfence();
        }
    }
    __syncthreads();
}

#define CLUSTER_SYNC() do { \
    asm volatile("barrier.cluster.arrive.aligned;" ::: "memory"); \
    asm volatile("barrier.cluster.wait.aligned;"   ::: "memory"); \
} while(0)

// ------------------------- generic SGEMM (f32x2 core) ------------------------
// C = A @ op(B) (+bias). BT=true: B is (N,K) row-major (X@W.T). 64x64 tile.
template<bool BT, bool BF16OUT>
__global__ void __launch_bounds__(256)
sgemm(const float* __restrict__ A, const float* __restrict__ Bw,
      const float* __restrict__ bias, void* __restrict__ Cv,
      int K, int lda, int ldb, int ldc)
{
    __shared__ float As[16][65];
    __shared__ __align__(8) float Bs[16][66];
    const int n0 = blockIdx.x * 64;
    const int m0 = blockIdx.y * 64;
    const int tid = threadIdx.x;
    const int tx = tid & 15, ty = tid >> 4;     // 16 x 16
    ull acc[4][2];
#pragma unroll
    for (int i=0;i<4;i++){ acc[i][0]=fdup(0.f); acc[i][1]=fdup(0.f); }

    for (int k0 = 0; k0 < K; k0 += 16){
#pragma unroll 4
        for (int i = tid; i < 1024; i += 256){
            int mm = i >> 4, kk = i & 15;
            As[kk][mm] = A[(size_t)(m0+mm)*lda + k0 + kk];
        }
        if (BT){
#pragma unroll 4
            for (int i = tid; i < 1024; i += 256){
                int nn = i >> 4, kk = i & 15;
                Bs[kk][nn] = Bw[(size_t)(n0+nn)*ldb + k0 + kk];
            }
        } else {
#pragma unroll 4
            for (int i = tid; i < 1024; i += 256){
                int kk = i >> 6, nn = i & 63;
                Bs[kk][nn] = Bw[(size_t)(k0+kk)*ldb + n0 + nn];
            }
        }
        __syncthreads();
#pragma unroll
        for (int kk = 0; kk < 16; kk++){
            ull a2[4], b2[2];
#pragma unroll
            for (int i=0;i<4;i++) a2[i] = fdup(As[kk][ty + 16*i]);
            b2[0] = *(const ull*)&Bs[kk][2*tx];
            b2[1] = *(const ull*)&Bs[kk][2*tx + 32];
#pragma unroll
            for (int i=0;i<4;i++){
                fma2(acc[i][0], a2[i], b2[0]);
                fma2(acc[i][1], a2[i], b2[1]);
            }
        }
        __syncthreads();
    }
#pragma unroll
    for (int i=0;i<4;i++){
        int m = m0 + ty + 16*i;
#pragma unroll
        for (int jp=0;jp<2;jp++){
            int n = n0 + 2*tx + 32*jp;
            float2 v = upk(acc[i][jp]);
            if (bias){ v.x += bias[n]; v.y += bias[n+1]; }
            if (BF16OUT){
                __nv_bfloat16* C = (__nv_bfloat16*)Cv;
                *(__nv_bfloat162*)&C[(size_t)m*ldc + n] = __float22bfloat162_rn(v);
            } else {
                float* C = (float*)Cv;
                *(float2*)&C[(size_t)m*ldc + n] = v;
            }
        }
    }
}

// ------------------------- fused prep ----------------------------------------
__global__ void k_prep(const int* __restrict__ src, const int* __restrict__ trg,
                       const float* __restrict__ enc_emb,
                       const float* __restrict__ dec_emb,
                       const float* __restrict__ dec_Wih,
                       const float* __restrict__ dec_Whh,
                       float* __restrict__ out)
{
    size_t idx = (size_t)blockIdx.x*256 + threadIdx.x;
    if (idx < (size_t)SS*BB*EE){
        int e = idx & 127, b = (idx >> 7) & 127, s = idx >> 14;
        g_embSB[idx] = enc_emb[(size_t)src[b*SS + s]*EE + e];
    }
    if (idx < (size_t)TT*BB*EE){
        int e = idx & 127, b = (idx >> 7) & 127, t = idx >> 14;
        g_embTB[idx] = dec_emb[(size_t)trg[b*128 + t]*EE + e];
    }
    if (idx < (size_t)2048*1024){
        int n = idx >> 10, k = idx & 1023;
        g_wcat[idx] = (k < 512) ? dec_Wih[(size_t)n*640 + 128 + k]
                                : dec_Whh[(size_t)n*512 + k - 512];
    }
    if (idx < 2*BB*HH) (&g_h_enc[0][0][0])[idx] = 0.f;
    if (idx < BB*128){
        int b = idx >> 7, v = idx & 127;
        out[(size_t)b*16384 + v] = 0.f;
    }
}

// ------------------------- persistent encoder --------------------------------
// 128 blocks x 128 threads, clusters of 8 (one per (dir, b-tile) group).
// j-tile = 32 cells x4 gates; Whh slice cached in smem; c in registers.
__global__ void __launch_bounds__(128) __cluster_dims__(8, 1, 1)
k_encoder(const float* __restrict__ Whh_f, const float* __restrict__ Whh_b)
{
    extern __shared__ float ws[];        // 256*129
    __shared__ float hs[16][17];
    const int bx  = blockIdx.x;
    const int jt  = bx & 7, bt = (bx >> 3) & 7, dir = bx >> 6;
    const int j0  = jt*32, b0 = bt*16;
    const int tid = threadIdx.x;
    const int tx  = tid & 31, ty = tid >> 5;
    const float* __restrict__ Whh = dir ? Whh_b : Whh_f;
    const float* __restrict__ xw  = dir ? g_xw_b : g_xw_f;

    for (int i = tid; i < 32768; i += 128){
        int k = i & 255, nl = i >> 8;
        ws[k*129 + nl] = Whh[(size_t)((nl>>5)*256 + j0 + (nl&31))*256 + k];
    }
    __syncthreads();

    float cr[4] = {0.f, 0.f, 0.f, 0.f};
    int p = 0;
    const int j = j0 + tx;

    for (int s = 0; s < 512; s++){
        const int sa = dir ? (511 - s) : s;
        const float* __restrict__ hin = g_h_enc[p][dir];
        float acc[4][4];
#pragma unroll
        for (int g=0; g<4; g++)
#pragma unroll
            for (int bi=0; bi<4; bi++) acc[g][bi] = 0.f;

        for (int k0 = 0; k0 < 256; k0 += 16){
            {
                int kk0 = tid & 15, bb0 = tid >> 4;
                hs[kk0][bb0] = __ldcg(&hin[(b0+bb0)*256 + k0 + kk0]);
                int i1 = tid + 128;
                int kk1 = i1 & 15, bb1 = i1 >> 4;
                hs[kk1][bb1] = __ldcg(&hin[(b0+bb1)*256 + k0 + kk1]);
            }
            __syncthreads();
#pragma unroll
            for (int kk = 0; kk < 16; kk++){
                const float* w = ws + (size_t)(k0+kk)*129;
                float a0 = hs[kk][ty],   a1 = hs[kk][ty+4];
                float a2 = hs[kk][ty+8], a3 = hs[kk][ty+12];
                float w0 = w[tx], w1 = w[32+tx], w2 = w[64+tx], w3 = w[96+tx];
                acc[0][0]=fmaf(w0,a0,acc[0][0]); acc[0][1]=fmaf(w0,a1,acc[0][1]);
                acc[0][2]=fmaf(w0,a2,acc[0][2]); acc[0][3]=fmaf(w0,a3,acc[0][3]);
                acc[1][0]=fmaf(w1,a0,acc[1][0]); acc[1][1]=fmaf(w1,a1,acc[1][1]);
                acc[1][2]=fmaf(w1,a2,acc[1][2]); acc[1][3]=fmaf(w1,a3,acc[1][3]);
                acc[2][0]=fmaf(w2,a0,acc[2][0]); acc[2][1]=fmaf(w2,a1,acc[2][1]);
                acc[2][2]=fmaf(w2,a2,acc[2][2]); acc[2][3]=fmaf(w2,a3,acc[2][3]);
                acc[3][0]=fmaf(w3,a0,acc[3][0]); acc[3][1]=fmaf(w3,a1,acc[3][1]);
                acc[3][2]=fmaf(w3,a2,acc[3][2]); acc[3][3]=fmaf(w3,a3,acc[3][3]);
            }
            __syncthreads();
        }

        float* __restrict__ hout = g_h_enc[p^1][dir];
#pragma unroll
        for (int bi = 0; bi < 4; bi++){
            int b = b0 + ty + 4*bi;
            const float* xwb = xw + ((size_t)sa*128 + b)*1024 + j;
            float ig = fsig (acc[0][bi] + xwb[0]);
            float fg = fsig (acc[1][bi] + xwb[256]);
            float gg = ftanh(acc[2][bi] + xwb[512]);
            float og = fsig (acc[3][bi] + xwb[768]);
            float cn = fmaf(fg, cr[bi], ig*gg);
            cr[bi] = cn;
            float hn = og * ftanh(cn);
            hout[b*256 + j] = hn;
            size_t eo = ((size_t)b*512 + sa)*512 + dir*256 + j;
            g_encout[eo] = hn;
            ((__nv_bfloat16*)g_encout_bf)[eo] = __float2bfloat16(hn);
        }
        p ^= 1;
        if (s < 511){
            CLUSTER_SYNC();
        } else {
#pragma unroll
            for (int bi = 0; bi < 4; bi++)
                g_c_enc[dir][(b0 + ty + 4*bi)*256 + j] = cr[bi];
        }
    }
}

// ------------------------- decoder tile GEMM (f32x2) -------------------------
// BM=32, 256 threads (16x16), TM=2, TN in {2,4}, BN=16*TN.
template<int TN>
__device__ void tile_gemm(const float* __restrict__ A, int lda,
                          const float* __restrict__ B, int ldb, bool bt, int K,
                          int m0, int n0,
                          const float* __restrict__ bias,
                          const float* __restrict__ Dadd, int ldd,
                          float* __restrict__ C, int ldc)
{
    constexpr int BN = 16*TN;
    constexpr int NP = TN/2;
    __shared__ float As[16][34];
    __shared__ __align__(8) float Bs[16][BN+2];
    const int tid = threadIdx.x;
    const int tx = tid & 15, ty = tid >> 4;
    ull acc[2][NP];
#pragma unroll
    for (int i=0;i<2;i++)
#pragma unroll
        for (int jp=0;jp<NP;jp++) acc[i][jp] = fdup(0.f);

    for (int k0 = 0; k0 < K; k0 += 16){
#pragma unroll
        for (int i = tid; i < 512; i += 256){
            int mm = i >> 4, kk = i & 15;
            As[kk][mm] = __ldcg(&A[(size_t)(m0+mm)*lda + k0 + kk]);
        }
        if (bt){
#pragma unroll
            for (int i = tid; i < 16*BN; i += 256){
                int nn = i >> 4, kk = i & 15;
                Bs[kk][nn] = B[(size_t)(n0+nn)*ldb + k0 + kk];
            }
        } else {
#pragma unroll
            for (int i = tid; i < 16*BN; i += 256){
                int kk = i / BN, nn = i % BN;
                Bs[kk][nn] = B[(size_t)(k0+kk)*ldb + n0 + nn];
            }
        }
        __syncthreads();
#pragma unroll
        for (int kk = 0; kk < 16; kk++){
            ull a0 = fdup(As[kk][ty]);
            ull a1 = fdup(As[kk][ty+16]);
#pragma unroll
            for (int jp = 0; jp < NP; jp++){
                ull bv = *(const ull*)&Bs[kk][2*tx + 32*jp];
                fma2(acc[0][jp], a0, bv);
                fma2(acc[1][jp], a1, bv);
            }
        }
        __syncthreads();
    }
#pragma unroll
    for (int i = 0; i < 2; i++){
        int m = m0 + ty + 16*i;
#pragma unroll
        for (int jp = 0; jp < NP; jp++){
            int n = n0 + 2*tx + 32*jp;
            float2 v = upk(acc[i][jp]);
            if (bias){ v.x += bias[n]; v.y += bias[n+1]; }
            if (Dadd){
                float2 d = *(const float2*)&Dadd[(size_t)m*ldd + n];
                v.x += d.x; v.y += d.y;
            }
            *(float2*)&C[(size_t)m*ldc + n] = v;
        }
    }
}

// ------------------------- decoder attention (bf16 streams) ------------------
__device__ void attention(int b, const float* __restrict__ attn_v)
{
    __shared__ float qsh[512];
    __shared__ float sc[512];
    __shared__ float red[8];
    const int tid = threadIdx.x, lane = tid & 31, warp = tid >> 5;

    for (int e = tid; e < 512; e += 256) qsh[e] = __ldcg(&g_q[b*512 + e]);
    __syncthreads();

    float2 av2[8];
#pragma unroll
    for (int i = 0; i < 8; i++){
        int e2 = lane + 32*i;
        av2[i] = *(const float2*)&attn_v[2*e2];
    }

    const __nv_bfloat162* __restrict__ proj = g_encproj + (size_t)b*512*256;
    for (int s = warp; s < 512; s += 8){
        const __nv_bfloat162* pr = proj + (size_t)s*256;
        float acc = 0.f;
#pragma unroll
        for (int i = 0; i < 8; i++){
            int e2 = lane + 32*i;
            float2 p = __bfloat1622float2(pr[e2]);
            float2 q = *(const float2*)&qsh[2*e2];
            acc = fmaf(av2[i].x, tanha(q.x + p.x), acc);
            acc = fmaf(av2[i].y, tanha(q.y + p.y), acc);
        }
#pragma unroll
        for (int o = 16; o; o >>= 1) acc += __shfl_xor_sync(~0u, acc, o);
        if (lane == 0) sc[s] = acc;
    }
    __syncthreads();

    float v0 = sc[tid], v1 = sc[tid + 256];
    float m = fmaxf(v0, v1);
#pragma unroll
    for (int o = 16; o; o >>= 1) m = fmaxf(m, __shfl_xor_sync(~0u, m, o));
    if (lane == 0) red[warp] = m;
    __syncthreads();
    m = red[0];
#pragma unroll
    for (int i = 1; i < 8; i++) m = fmaxf(m, red[i]);
    __syncthreads();
    float e0 = __expf(v0 - m), e1 = __expf(v1 - m);
    float ssum = e0 + e1;
#pragma unroll
    for (int o = 16; o; o >>= 1) ssum += __shfl_xor_sync(~0u, ssum, o);
    if (lane == 0) red[warp] = ssum;
    __syncthreads();
    ssum = 0.f;
#pragma unroll
    for (int i = 0; i < 8; i++) ssum += red[i];
    float inv = __fdividef(1.f, ssum);
    sc[tid] = e0*inv;
    sc[tid + 256] = e1*inv;
    __syncthreads();

    const __nv_bfloat162* __restrict__ eo = g_encout_bf + (size_t)b*512*256;
    float c0 = 0.f, c1 = 0.f;
#pragma unroll 8
    for (int s = 0; s < 512; s++){
        float w = sc[s];
        float2 f = __bfloat1622float2(eo[(size_t)s*256 + tid]);
        c0 = fmaf(w, f.x, c0);
        c1 = fmaf(w, f.y, c1);
    }
    float2 cv = {c0, c1};
    *(float2*)&g_u[b*1024 + 2*tid] = cv;
    __syncthreads();
}

// ------------------------- persistent decoder --------------------------------
__global__ void __launch_bounds__(256)
k_decoder(const float* __restrict__ attn_W, const float* __restrict__ attn_v,
          const float* __restrict__ out_W, const float* __restrict__ out_b,
          float* __restrict__ out)
{
    const int bid = blockIdx.x, tid = threadIdx.x;
    float cr[2];
#pragma unroll
    for (int r = 0; r < 2; r++){
        int idx = bid*256 + tid + r*32768;
        int b = idx >> 9, j = idx & 511;
        float h, c;
        if (j < 256){ h = g_h_enc[0][0][b*256 + j];       c = g_c_enc[0][b*256 + j]; }
        else        { h = g_h_enc[0][1][b*256 + j - 256]; c = g_c_enc[1][b*256 + j - 256]; }
        g_u[b*1024 + 512 + j] = h;
        cr[r] = c;
    }
    dbar();

    for (int t = 0; t < TT; t++){
        // ---- phase A: q = h@Wh; logits(prev h) for t>0 ----
        if (bid < 64){
            int mt = bid & 3, nt = bid >> 2;
            tile_gemm<2>(g_u + 512, 1024, attn_W, 512, false, 512,
                         mt*32, nt*32, nullptr, nullptr, 0, g_q, 512);
        } else if (bid < 80 && t > 0){
            int q = bid - 64, mt = q & 3, nt = q >> 2;
            tile_gemm<2>(g_u + 512, 1024, out_W, 128, false, 512,
                         mt*32, nt*32, out_b, nullptr, 0,
                         out + (size_t)t*128, 16384);
        }
        dbar();
        // ---- phase B: attention ----
        attention(bid, attn_v);
        dbar();
        // ---- phase C: gates = [ctx|h]@wcat^T + xg[t] ----
        {
            int mt = bid & 3, nt = bid >> 2;
            tile_gemm<4>(g_u, 1024, g_wcat, 1024, true, 1024,
                         mt*32, nt*64, nullptr,
                         g_xg + (size_t)t*BB*2048, 2048, g_gates, 2048);
        }
        dbar();
        // ---- phase D: LSTM cell ----
#pragma unroll
        for (int r = 0; r < 2; r++){
            int idx = bid*256 + tid + r*32768;
            int b = idx >> 9, j = idx & 511;
            const float* gg = g_gates + b*2048;
            float ig = fsig (__ldcg(&gg[j]));
            float fg = fsig (__ldcg(&gg[512  + j]));
            float g2 = ftanh(__ldcg(&gg[1024 + j]));
            float og = fsig (__ldcg(&gg[1536 + j]));
            float cn = fmaf(fg, cr[r], ig*g2);
            cr[r] = cn;
            g_u[b*1024 + 512 + j] = og * ftanh(cn);
        }
        dbar();
    }
    // final logits -> out[:, 127]
    if (bid < 16){
        int mt = bid & 3, nt = bid >> 2;
        tile_gemm<2>(g_u + 512, 1024, out_W, 128, false, 512,
                     mt*32, nt*32, out_b, nullptr, 0,
                     out + (size_t)TT*128, 16384);
    }
}

// ------------------------- launch --------------------------------------------
extern "C" void kernel_launch(void* const* d_in, const int* in_sizes, int n_in,
                              void* d_out, int out_size)
{
    const int*   src     = (const int*)  d_in[0];
    const int*   trg     = (const int*)  d_in[1];
    const float* enc_emb = (const float*)d_in[2];
    const float* Wih_f   = (const float*)d_in[3];
    const float* Whh_f   = (const float*)d_in[4];
    const float* b_f     = (const float*)d_in[5];
    const float* Wih_b   = (const float*)d_in[6];
    const float* Whh_b   = (const float*)d_in[7];
    const float* b_b     = (const float*)d_in[8];
    const float* dec_emb = (const float*)d_in[9];
    const float* dec_Wih = (const float*)d_in[10];
    const float* dec_Whh = (const float*)d_in[11];
    const float* dec_b   = (const float*)d_in[12];
    const float* attn_W  = (const float*)d_in[13];
    const float* attn_b  = (const float*)d_in[14];
    const float* attn_v  = (const float*)d_in[15];
    const float* out_W   = (const float*)d_in[16];
    const float* out_b   = (const float*)d_in[17];
    float* out = (float*)d_out;

    float *p_embSB, *p_embTB, *p_xw_f, *p_xw_b, *p_encout, *p_xg;
    void  *p_encproj;
    cudaGetSymbolAddress((void**)&p_embSB,  g_embSB);
    cudaGetSymbolAddress((void**)&p_embTB,  g_embTB);
    cudaGetSymbolAddress((void**)&p_xw_f,   g_xw_f);
    cudaGetSymbolAddress((void**)&p_xw_b,   g_xw_b);
    cudaGetSymbolAddress((void**)&p_encout, g_encout);
    cudaGetSymbolAddress(&p_encproj,        g_encproj);
    cudaGetSymbolAddress((void**)&p_xg,     g_xg);

    cudaFuncSetAttribute(k_encoder,
        cudaFuncAttributeMaxDynamicSharedMemorySize, 256*129*4);

    // 1) fused prep
    k_prep<<<(SS*BB*EE)/256, 256>>>(src, trg, enc_emb, dec_emb,
                                    dec_Wih, dec_Whh, out);
    // 2-4) precompute GEMMs
    sgemm<true,false><<<dim3(1024/64, (SS*BB)/64), 256>>>(
        p_embSB, Wih_f, b_f, p_xw_f, EE, EE, EE, 1024);
    sgemm<true,false><<<dim3(1024/64, (SS*BB)/64), 256>>>(
        p_embSB, Wih_b, b_b, p_xw_b, EE, EE, EE, 1024);
    sgemm<true,false><<<dim3(2048/64, (TT*BB)/64), 256>>>(
        p_embTB, dec_Wih, dec_b, p_xg, EE, EE, 640, 2048);
    // 5) persistent encoder (clusters of 8)
    k_encoder<<<128, 128, 256*129*4>>>(Whh_f, Whh_b);
    // 6) enc_proj = enc_out @ We + attn_b  (bf16 out)
    sgemm<false,true><<<dim3(512/64, (BB*SS)/64), 256>>>(
        p_encout, attn_W + 512*512, attn_b, p_encproj, 512, 512, 512, 512);
    // 7) persistent decoder
    k_decoder<<<128, 256>>>(attn_W, attn_v, out_W, out_b, out);
}

// round 8
// speedup vs baseline: 1.9994x; 1.9094x over previous
#include <cuda_runtime.h>
#include <cuda_bf16.h>
#include <cstdint>
#include <cstddef>

#define BB  128
#define SS  512
#define EE  128
#define HH  256
#define HD  512
#define TT  127

typedef unsigned long long ull;

// ------------------------- device scratch ------------------------------------
__device__ float g_embSB[(size_t)SS*BB*EE];
__device__ float g_embTB[(size_t)TT*BB*EE];
__device__ float g_xw_f[(size_t)SS*BB*4*HH];
__device__ float g_xw_b[(size_t)SS*BB*4*HH];
__device__ float g_h_enc[2][2][BB*HH];                 // [parity][dir]
__device__ float g_c_enc[2][BB*HH];                    // final cells [dir]
__device__ float g_encout[(size_t)BB*SS*2*HH];         // fp32 (b,s,512)
__device__ __nv_bfloat162 g_encout_bf[(size_t)BB*SS*256];
__device__ __nv_bfloat162 g_encproj[(size_t)BB*SS*256];  // bf16 + attn_b
__device__ float g_xg[(size_t)TT*BB*4*HD];
__device__ float g_wcat[(size_t)4*HD*1024];            // [Wih_ctx | Whh]
__device__ float g_u[BB*1024];                         // [ctx(512) | h(512)]
__device__ float g_gates[BB*4*HD];
__device__ float g_q[BB*HD];

__device__ unsigned g_dbar_cnt;
__device__ volatile unsigned g_dbar_gen;

// ------------------------- math helpers --------------------------------------
__device__ __forceinline__ float ftanh(float x){
    float e = __expf(2.f*x);
    return 1.f - __fdividef(2.f, e + 1.f);
}
__device__ __forceinline__ float fsig(float x){
    return __fdividef(1.f, 1.f + __expf(-x));
}
__device__ __forceinline__ float tanha(float x){
    float y; asm("tanh.approx.f32 %0, %1;" : "=f"(y) : "f"(x)); return y;
}
__device__ __forceinline__ ull fdup(float x){
    ull r; asm("mov.b64 %0, {%1, %1};" : "=l"(r) : "f"(x)); return r;
}
__device__ __forceinline__ void fma2(ull& d, ull a, ull b){
    asm("fma.rn.f32x2 %0, %1, %2, %0;" : "+l"(d) : "l"(a), "l"(b));
}
__device__ __forceinline__ float2 upk(ull v){
    float2 f; asm("mov.b64 {%0, %1}, %2;" : "=f"(f.x), "=f"(f.y) : "l"(v));
    return f;
}

__device__ __forceinline__ void dbar(){
    __syncthreads();
    if (threadIdx.x == 0){
        unsigned g = g_dbar_gen;
        __threadfence();
        if (atomicAdd(&g_dbar_cnt, 1u) == 127u){
            g_dbar_cnt = 0u;
            __threadfence();
            g_dbar_gen = g + 1u;
        } else {
            while (g_dbar_gen == g) __nanosleep(32);
            __threadfence();
        }
    }
    __syncthreads();
}

#define CLUSTER_SYNC() do { \
    asm volatile("barrier.cluster.arrive.aligned;" ::: "memory"); \
    asm volatile("barrier.cluster.wait.aligned;"   ::: "memory"); \
} while(0)

// ------------------------- precompute SGEMM (device body) --------------------
template<bool BT, bool BF16OUT>
__device__ __forceinline__ void
sgemm_dev(const float* __restrict__ A, const float* __restrict__ Bw,
          const float* __restrict__ bias, void* __restrict__ Cv,
          int K, int lda, int ldb, int ldc, int m0, int n0)
{
    __shared__ float As[16][65];
    __shared__ __align__(8) float Bs[16][66];
    const int tid = threadIdx.x;
    const int tx = tid & 15, ty = tid >> 4;
    ull acc[4][2];
#pragma unroll
    for (int i=0;i<4;i++){ acc[i][0]=fdup(0.f); acc[i][1]=fdup(0.f); }

    for (int k0 = 0; k0 < K; k0 += 16){
#pragma unroll 4
        for (int i = tid; i < 1024; i += 256){
            int mm = i >> 4, kk = i & 15;
            As[kk][mm] = A[(size_t)(m0+mm)*lda + k0 + kk];
        }
        if (BT){
#pragma unroll 4
            for (int i = tid; i < 1024; i += 256){
                int nn = i >> 4, kk = i & 15;
                Bs[kk][nn] = Bw[(size_t)(n0+nn)*ldb + k0 + kk];
            }
        } else {
#pragma unroll 4
            for (int i = tid; i < 1024; i += 256){
                int kk = i >> 6, nn = i & 63;
                Bs[kk][nn] = Bw[(size_t)(k0+kk)*ldb + n0 + nn];
            }
        }
        __syncthreads();
#pragma unroll
        for (int kk = 0; kk < 16; kk++){
            ull a2[4], b2[2];
#pragma unroll
            for (int i=0;i<4;i++) a2[i] = fdup(As[kk][ty + 16*i]);
            b2[0] = *(const ull*)&Bs[kk][2*tx];
            b2[1] = *(const ull*)&Bs[kk][2*tx + 32];
#pragma unroll
            for (int i=0;i<4;i++){
                fma2(acc[i][0], a2[i], b2[0]);
                fma2(acc[i][1], a2[i], b2[1]);
            }
        }
        __syncthreads();
    }
#pragma unroll
    for (int i=0;i<4;i++){
        int m = m0 + ty + 16*i;
#pragma unroll
        for (int jp=0;jp<2;jp++){
            int n = n0 + 2*tx + 32*jp;
            float2 v = upk(acc[i][jp]);
            if (bias){ v.x += bias[n]; v.y += bias[n+1]; }
            if (BF16OUT){
                __nv_bfloat16* C = (__nv_bfloat16*)Cv;
                *(__nv_bfloat162*)&C[(size_t)m*ldc + n] = __float22bfloat162_rn(v);
            } else {
                float* C = (float*)Cv;
                *(float2*)&C[(size_t)m*ldc + n] = v;
            }
        }
    }
}

template<bool BT, bool BF16OUT>
__global__ void __launch_bounds__(256)
sgemm(const float* __restrict__ A, const float* __restrict__ Bw,
      const float* __restrict__ bias, void* __restrict__ Cv,
      int K, int lda, int ldb, int ldc)
{
    sgemm_dev<BT,BF16OUT>(A, Bw, bias, Cv, K, lda, ldb, ldc,
                          blockIdx.y*64, blockIdx.x*64);
}

// fused forward/backward encoder-gate GEMM (z selects weight set)
__global__ void __launch_bounds__(256)
sgemm_enc(const float* __restrict__ A,
          const float* __restrict__ Wf, const float* __restrict__ bf_,
          float* __restrict__ Cf,
          const float* __restrict__ Wb, const float* __restrict__ bb_,
          float* __restrict__ Cb)
{
    const float* W  = blockIdx.z ? Wb  : Wf;
    const float* bs = blockIdx.z ? bb_ : bf_;
    float*       C  = blockIdx.z ? Cb  : Cf;
    sgemm_dev<true,false>(A, W, bs, C, EE, EE, EE, 1024,
                          blockIdx.y*64, blockIdx.x*64);
}

// ------------------------- fused prep ----------------------------------------
__global__ void k_prep(const int* __restrict__ src, const int* __restrict__ trg,
                       const float* __restrict__ enc_emb,
                       const float* __restrict__ dec_emb,
                       const float* __restrict__ dec_Wih,
                       const float* __restrict__ dec_Whh,
                       float* __restrict__ out)
{
    size_t idx = (size_t)blockIdx.x*256 + threadIdx.x;
    if (idx < (size_t)SS*BB*EE){
        int e = idx & 127, b = (idx >> 7) & 127, s = idx >> 14;
        g_embSB[idx] = enc_emb[(size_t)src[b*SS + s]*EE + e];
    }
    if (idx < (size_t)TT*BB*EE){
        int e = idx & 127, b = (idx >> 7) & 127, t = idx >> 14;
        g_embTB[idx] = dec_emb[(size_t)trg[b*128 + t]*EE + e];
    }
    if (idx < (size_t)2048*1024){
        int n = idx >> 10, k = idx & 1023;
        g_wcat[idx] = (k < 512) ? dec_Wih[(size_t)n*640 + 128 + k]
                                : dec_Whh[(size_t)n*512 + k - 512];
    }
    if (idx < 2*BB*HH) (&g_h_enc[0][0][0])[idx] = 0.f;
    if (idx < BB*128){
        int b = idx >> 7, v = idx & 127;
        out[(size_t)b*16384 + v] = 0.f;
    }
}

// ------------------------- persistent encoder --------------------------------
// 128 blocks x 256 threads, clusters of 8 (= one (dir,b-tile) group).
// block tile: 32 j x 4 gates x 16 b, K=256. Whh slice in smem (once).
// Per step: stage full h-tile to smem (single latency exposure), then
// f32x2 inner loop (gate-pairs x row): 4 fma2 per k for 16 MACs.
__global__ void __launch_bounds__(256) __cluster_dims__(8, 1, 1)
k_encoder(const float* __restrict__ Whh_f, const float* __restrict__ Whh_b)
{
    extern __shared__ float ws[];            // 256*132 floats (135168 B)
    __shared__ float hsf[256*18];            // h tile [k][b], padded
    const int bx  = blockIdx.x;
    const int jt  = bx & 7, bt = (bx >> 3) & 7, dir = bx >> 6;
    const int j0  = jt*32, b0 = bt*16;
    const int tid = threadIdx.x;
    const int tx  = tid & 31;                // j within tile
    const int ty  = tid >> 5;                // 0..7 -> rows (b0+2ty, b0+2ty+1)
    const float* __restrict__ Whh = dir ? Whh_b : Whh_f;
    const float* __restrict__ xw  = dir ? g_xw_b : g_xw_f;

    // weights: ws[k*132 + 4*jj + g]
#pragma unroll 4
    for (int i = tid; i < 32768; i += 256){
        int k = i & 255, nl = i >> 8;        // nl = 4*jj + g
        int jj = nl >> 2, g = nl & 3;
        ws[k*132 + nl] = Whh[(size_t)(g*256 + j0 + jj)*256 + k];
    }
    __syncthreads();

    float cr[2] = {0.f, 0.f};
    const int j = j0 + tx;

    for (int s = 0; s < 512; s++){
        const int sa = dir ? (511 - s) : s;
        const float* __restrict__ hin = g_h_enc[s & 1][dir];
        float* __restrict__ hout      = g_h_enc[(s & 1) ^ 1][dir];

        // stage h tile: 16 rows x 256 k (16 ldcg per thread, all in flight)
#pragma unroll
        for (int i = tid; i < 4096; i += 256){
            int b = i >> 8, k = i & 255;
            hsf[k*18 + b] = __ldcg(&hin[(b0 + b)*256 + k]);
        }
        __syncthreads();

        ull accA[2], accB[2];                // [row] x (g0,g1) / (g2,g3)
        accA[0]=fdup(0.f); accA[1]=fdup(0.f);
        accB[0]=fdup(0.f); accB[1]=fdup(0.f);

#pragma unroll 16
        for (int k = 0; k < 256; k++){
            const ull* wp = (const ull*)(ws + k*132 + 4*tx);
            ull w01 = wp[0], w23 = wp[1];
            float2 hp = *(const float2*)(hsf + k*18 + 2*ty);
            ull hd0 = fdup(hp.x), hd1 = fdup(hp.y);
            fma2(accA[0], w01, hd0);
            fma2(accB[0], w23, hd0);
            fma2(accA[1], w01, hd1);
            fma2(accB[1], w23, hd1);
        }
        __syncthreads();

#pragma unroll
        for (int r = 0; r < 2; r++){
            int b = b0 + 2*ty + r;
            float2 g01 = upk(accA[r]);
            float2 g23 = upk(accB[r]);
            const float* xwb = xw + ((size_t)sa*128 + b)*1024 + j;
            float ig = fsig (g01.x + xwb[0]);
            float fg = fsig (g01.y + xwb[256]);
            float gg = ftanh(g23.x + xwb[512]);
            float og = fsig (g23.y + xwb[768]);
            float cn = fmaf(fg, cr[r], ig*gg);
            cr[r] = cn;
            float hn = og * ftanh(cn);
            hout[b*256 + j] = hn;
            size_t eo = ((size_t)b*512 + sa)*512 + dir*256 + j;
            g_encout[eo] = hn;
            ((__nv_bfloat16*)g_encout_bf)[eo] = __float2bfloat16(hn);
        }
        if (s < 511){
            CLUSTER_SYNC();
        } else {
#pragma unroll
            for (int r = 0; r < 2; r++)
                g_c_enc[dir][(b0 + 2*ty + r)*256 + j] = cr[r];
        }
    }
}

// ------------------------- decoder tile GEMM (512 thr, prefetch) -------------
// 32m x 64n tile. threads: tx 0..31 (n pairs), ty 0..15 (m = ty, ty+16).
template<bool BT>
__device__ void tg512(const float* __restrict__ A, int lda,
                      const float* __restrict__ B, int ldb, int K,
                      int m0, int n0,
                      const float* __restrict__ bias,
                      const float* __restrict__ Dadd, int ldd,
                      float* __restrict__ C, int ldc)
{
    __shared__ float As[16][33];
    __shared__ __align__(8) float Bs[16][66];
    const int tid = threadIdx.x;
    const int tx = tid & 31, ty = tid >> 5;
    ull acc0 = fdup(0.f), acc1 = fdup(0.f);

    // register prefetch staging
    const int a_mm = tid >> 4, a_kk = tid & 15;
    int b_nn0, b_kk0, b_nn1, b_kk1;
    if (BT){
        b_nn0 = tid >> 4;          b_kk0 = tid & 15;
        b_nn1 = (tid+512) >> 4;    b_kk1 = tid & 15;
    } else {
        b_kk0 = tid >> 6;          b_nn0 = tid & 63;
        b_kk1 = (tid+512) >> 6;    b_nn1 = tid & 63;
    }
    float ra, rb0, rb1;
    ra  = __ldcg(&A[(size_t)(m0+a_mm)*lda + a_kk]);
    if (BT){
        rb0 = B[(size_t)(n0+b_nn0)*ldb + b_kk0];
        rb1 = B[(size_t)(n0+b_nn1)*ldb + b_kk1];
    } else {
        rb0 = B[(size_t)b_kk0*ldb + n0 + b_nn0];
        rb1 = B[(size_t)b_kk1*ldb + n0 + b_nn1];
    }

    for (int k0 = 0; k0 < K; k0 += 16){
        As[a_kk][a_mm] = ra;
        Bs[b_kk0][b_nn0] = rb0;
        Bs[b_kk1][b_nn1] = rb1;
        __syncthreads();
        if (k0 + 16 < K){
            int kn = k0 + 16;
            ra  = __ldcg(&A[(size_t)(m0+a_mm)*lda + kn + a_kk]);
            if (BT){
                rb0 = B[(size_t)(n0+b_nn0)*ldb + kn + b_kk0];
                rb1 = B[(size_t)(n0+b_nn1)*ldb + kn + b_kk1];
            } else {
                rb0 = B[(size_t)(kn+b_kk0)*ldb + n0 + b_nn0];
                rb1 = B[(size_t)(kn+b_kk1)*ldb + n0 + b_nn1];
            }
        }
#pragma unroll
        for (int kk = 0; kk < 16; kk++){
            ull bv = *(const ull*)&Bs[kk][2*tx];
            fma2(acc0, fdup(As[kk][ty]),      bv);
            fma2(acc1, fdup(As[kk][ty + 16]), bv);
        }
        __syncthreads();
    }
    {
        int n = n0 + 2*tx;
        float2 v0 = upk(acc0), v1 = upk(acc1);
        if (bias){
            float2 bb = *(const float2*)&bias[n];
            v0.x += bb.x; v0.y += bb.y; v1.x += bb.x; v1.y += bb.y;
        }
        int ma = m0 + ty, mb = m0 + ty + 16;
        if (Dadd){
            float2 d0 = *(const float2*)&Dadd[(size_t)ma*ldd + n];
            float2 d1 = *(const float2*)&Dadd[(size_t)mb*ldd + n];
            v0.x += d0.x; v0.y += d0.y; v1.x += d1.x; v1.y += d1.y;
        }
        *(float2*)&C[(size_t)ma*ldc + n] = v0;
        *(float2*)&C[(size_t)mb*ldc + n] = v1;
    }
}

// ------------------------- decoder attention (512 thr) -----------------------
__device__ void attention(int b, const float* __restrict__ attn_v)
{
    __shared__ float qsh[512];
    __shared__ float sc[512];
    __shared__ float red[16];
    __shared__ float4 part[4][128];
    const int tid = threadIdx.x, lane = tid & 31, warp = tid >> 5;

    qsh[tid] = __ldcg(&g_q[b*512 + tid]);
    __syncthreads();

    float4 av[4], qv[4];
#pragma unroll
    for (int i = 0; i < 4; i++){
        av[i] = *(const float4*)&attn_v[4*(lane + 32*i)];
        qv[i] = *(const float4*)&qsh[4*(lane + 32*i)];
    }

    const __nv_bfloat162* __restrict__ proj = g_encproj + (size_t)b*512*256;
    for (int s = warp; s < 512; s += 16){
        const uint2* pr = (const uint2*)(proj + (size_t)s*256);
        float acc = 0.f;
#pragma unroll
        for (int i = 0; i < 4; i++){
            uint2 u = pr[lane + 32*i];
            float2 p0 = __bfloat1622float2(*(__nv_bfloat162*)&u.x);
            float2 p1 = __bfloat1622float2(*(__nv_bfloat162*)&u.y);
            acc = fmaf(av[i].x, tanha(qv[i].x + p0.x), acc);
            acc = fmaf(av[i].y, tanha(qv[i].y + p0.y), acc);
            acc = fmaf(av[i].z, tanha(qv[i].z + p1.x), acc);
            acc = fmaf(av[i].w, tanha(qv[i].w + p1.y), acc);
        }
#pragma unroll
        for (int o = 16; o; o >>= 1) acc += __shfl_xor_sync(~0u, acc, o);
        if (lane == 0) sc[s] = acc;
    }
    __syncthreads();

    float v = sc[tid];
    float m = v;
#pragma unroll
    for (int o = 16; o; o >>= 1) m = fmaxf(m, __shfl_xor_sync(~0u, m, o));
    if (lane == 0) red[warp] = m;
    __syncthreads();
    m = red[0];
#pragma unroll
    for (int i = 1; i < 16; i++) m = fmaxf(m, red[i]);
    __syncthreads();
    float ex = __expf(v - m);
    float ssum = ex;
#pragma unroll
    for (int o = 16; o; o >>= 1) ssum += __shfl_xor_sync(~0u, ssum, o);
    if (lane == 0) red[warp] = ssum;
    __syncthreads();
    ssum = 0.f;
#pragma unroll
    for (int i = 0; i < 16; i++) ssum += red[i];
    sc[tid] = ex * __fdividef(1.f, ssum);
    __syncthreads();

    // context: 4 s-quarters x 128 col-pairs
    const int q4 = tid >> 7, cp = tid & 127;
    const uint2* __restrict__ eo = (const uint2*)(g_encout_bf + (size_t)b*512*256);
    float4 ca = {0.f, 0.f, 0.f, 0.f};
#pragma unroll 4
    for (int s = q4*128; s < q4*128 + 128; s++){
        float w = sc[s];
        uint2 u = eo[(size_t)s*128 + cp];
        float2 f0 = __bfloat1622float2(*(__nv_bfloat162*)&u.x);
        float2 f1 = __bfloat1622float2(*(__nv_bfloat162*)&u.y);
        ca.x = fmaf(w, f0.x, ca.x);
        ca.y = fmaf(w, f0.y, ca.y);
        ca.z = fmaf(w, f1.x, ca.z);
        ca.w = fmaf(w, f1.y, ca.w);
    }
    part[q4][cp] = ca;
    __syncthreads();
    if (tid < 128){
        float4 p0 = part[0][tid], p1 = part[1][tid];
        float4 p2 = part[2][tid], p3 = part[3][tid];
        float4 r;
        r.x = p0.x + p1.x + p2.x + p3.x;
        r.y = p0.y + p1.y + p2.y + p3.y;
        r.z = p0.z + p1.z + p2.z + p3.z;
        r.w = p0.w + p1.w + p2.w + p3.w;
        *(float4*)&g_u[b*1024 + 4*tid] = r;
    }
    __syncthreads();
}

// ------------------------- persistent decoder (512 thr) ----------------------
__global__ void __launch_bounds__(512)
k_decoder(const float* __restrict__ attn_W, const float* __restrict__ attn_v,
          const float* __restrict__ out_W, const float* __restrict__ out_b,
          float* __restrict__ out)
{
    const int bid = blockIdx.x, tid = threadIdx.x;
    float cr;
    {
        int idx = bid*512 + tid;
        int b = idx >> 9, j = idx & 511;
        float h, c;
        if (j < 256){ h = g_h_enc[0][0][b*256 + j];       c = g_c_enc[0][b*256 + j]; }
        else        { h = g_h_enc[0][1][b*256 + j - 256]; c = g_c_enc[1][b*256 + j - 256]; }
        g_u[b*1024 + 512 + j] = h;
        cr = c;
    }
    dbar();

    for (int t = 0; t < TT; t++){
        // ---- phase A: q = h@Wh (32 blocks); logits(prev h) (8 blocks, t>0) ----
        if (bid < 32){
            int mt = bid & 3, nt = bid >> 2;
            tg512<false>(g_u + 512, 1024, attn_W, 512, 512,
                         mt*32, nt*64, nullptr, nullptr, 0, g_q, 512);
        } else if (bid < 40 && t > 0){
            int q = bid - 32, mt = q & 3, nt = q >> 2;
            tg512<false>(g_u + 512, 1024, out_W, 128, 512,
                         mt*32, nt*64, out_b, nullptr, 0,
                         out + (size_t)t*128, 16384);
        }
        dbar();
        // ---- phase B: attention ----
        attention(bid, attn_v);
        dbar();
        // ---- phase C: gates = [ctx|h] @ wcat^T + xg[t] ----
        {
            int mt = bid & 3, nt = bid >> 2;
            tg512<true>(g_u, 1024, g_wcat, 1024, 1024,
                        mt*32, nt*64, nullptr,
                        g_xg + (size_t)t*BB*2048, 2048, g_gates, 2048);
        }
        dbar();
        // ---- phase D: LSTM cell ----
        {
            int idx = bid*512 + tid;
            int b = idx >> 9, j = idx & 511;
            const float* gg = g_gates + b*2048;
            float ig = fsig (__ldcg(&gg[j]));
            float fg = fsig (__ldcg(&gg[512  + j]));
            float g2 = ftanh(__ldcg(&gg[1024 + j]));
            float og = fsig (__ldcg(&gg[1536 + j]));
            float cn = fmaf(fg, cr, ig*g2);
            cr = cn;
            g_u[b*1024 + 512 + j] = og * ftanh(cn);
        }
        dbar();
    }
    // final logits -> out[:, 127]
    if (bid < 8){
        int mt = bid & 3, nt = bid >> 2;
        tg512<false>(g_u + 512, 1024, out_W, 128, 512,
                     mt*32, nt*64, out_b, nullptr, 0,
                     out + (size_t)TT*128, 16384);
    }
}

// ------------------------- launch --------------------------------------------
extern "C" void kernel_launch(void* const* d_in, const int* in_sizes, int n_in,
                              void* d_out, int out_size)
{
    const int*   src     = (const int*)  d_in[0];
    const int*   trg     = (const int*)  d_in[1];
    const float* enc_emb = (const float*)d_in[2];
    const float* Wih_f   = (const float*)d_in[3];
    const float* Whh_f   = (const float*)d_in[4];
    const float* b_f     = (const float*)d_in[5];
    const float* Wih_b   = (const float*)d_in[6];
    const float* Whh_b   = (const float*)d_in[7];
    const float* b_b     = (const float*)d_in[8];
    const float* dec_emb = (const float*)d_in[9];
    const float* dec_Wih = (const float*)d_in[10];
    const float* dec_Whh = (const float*)d_in[11];
    const float* dec_b   = (const float*)d_in[12];
    const float* attn_W  = (const float*)d_in[13];
    const float* attn_b  = (const float*)d_in[14];
    const float* attn_v  = (const float*)d_in[15];
    const float* out_W   = (const float*)d_in[16];
    const float* out_b   = (const float*)d_in[17];
    float* out = (float*)d_out;

    float *p_embSB, *p_embTB, *p_xw_f, *p_xw_b, *p_encout, *p_xg;
    void  *p_encproj;
    cudaGetSymbolAddress((void**)&p_embSB,  g_embSB);
    cudaGetSymbolAddress((void**)&p_embTB,  g_embTB);
    cudaGetSymbolAddress((void**)&p_xw_f,   g_xw_f);
    cudaGetSymbolAddress((void**)&p_xw_b,   g_xw_b);
    cudaGetSymbolAddress((void**)&p_encout, g_encout);
    cudaGetSymbolAddress(&p_encproj,        g_encproj);
    cudaGetSymbolAddress((void**)&p_xg,     g_xg);

    cudaFuncSetAttribute(k_encoder,
        cudaFuncAttributeMaxDynamicSharedMemorySize, 256*132*4);

    // 0) fused prep
    k_prep<<<(SS*BB*EE)/256, 256>>>(src, trg, enc_emb, dec_emb,
                                    dec_Wih, dec_Whh, out);
    // 1) encoder input-gate GEMMs (fwd+bwd fused via z)
    sgemm_enc<<<dim3(1024/64, (SS*BB)/64, 2), 256>>>(
        p_embSB, Wih_f, b_f, p_xw_f, Wih_b, b_b, p_xw_b);
    // 2) decoder emb-gate GEMM
    sgemm<true,false><<<dim3(2048/64, (TT*BB)/64), 256>>>(
        p_embTB, dec_Wih, dec_b, p_xg, EE, EE, 640, 2048);
    // 3) persistent encoder
    k_encoder<<<128, 256, 256*132*4>>>(Whh_f, Whh_b);
    // 4) enc_proj = enc_out @ We + attn_b (bf16 out)
    sgemm<false,true><<<dim3(512/64, (BB*SS)/64), 256>>>(
        p_encout, attn_W + 512*512, attn_b, p_encproj, 512, 512, 512, 512);
    // 5) persistent decoder  (ncu -s 5 -c 1 lands here)
    k_decoder<<<128, 512>>>(attn_W, attn_v, out_W, out_b, out);
}